// round 13
// baseline (speedup 1.0000x reference)
#include <cuda_runtime.h>

#define N_NODES  50000
#define N_EDGES  800000
#define N_GRAPHS 64
#define HID      64

#define CHUNK 256
#define NBLK ((N_NODES + CHUNK - 1) / CHUNK)   // 196

// ---------------- scratch (device globals; no allocation) ----------------
__device__ int   g_in_deg[N_NODES];
__device__ int   g_out_deg[N_NODES];
__device__ float g_norm_src[N_NODES];
__device__ float g_norm_dst[N_NODES];
__device__ float g_h0n[N_NODES];          // in_deg * norm_src (pre-scaled layer-0 input)
__device__ int   g_row_off[N_NODES + 1];
__device__ int   g_cursor[N_NODES];
__device__ int   g_edge_src[N_EDGES];
__device__ float g_hA[N_NODES * HID];
__device__ float g_hB[N_NODES * HID];
__device__ float g_hg[N_GRAPHS * HID];
__device__ float g_cnt[N_GRAPHS];
__device__ int   g_part[NBLK];
__device__ int   g_partoff[NBLK];

// ---------------- init ----------------
__global__ void k_zero() {
    int i = blockIdx.x * blockDim.x + threadIdx.x;
    if (i < N_NODES) { g_in_deg[i] = 0; g_out_deg[i] = 0; }
    if (i < N_GRAPHS * HID) g_hg[i] = 0.f;
    if (i < N_GRAPHS) g_cnt[i] = 0.f;
}

__global__ void k_deg(const int* __restrict__ src, const int* __restrict__ dst) {
    int i = blockIdx.x * blockDim.x + threadIdx.x;
    if (i < N_EDGES) {
        atomicAdd(&g_in_deg[dst[i]], 1);
        atomicAdd(&g_out_deg[src[i]], 1);
    }
}

// ---------------- prep: norms + h0n + graph counts + scan partials (fused) ----------------
__global__ void k_prep(const int* __restrict__ n2g) {
    __shared__ int s[CHUNK];
    int t = threadIdx.x;
    int idx = blockIdx.x * CHUNK + t;
    int id = 0;
    if (idx < N_NODES) {
        id = g_in_deg[idx];
        int od = g_out_deg[idx];
        float ns = rsqrtf((float)(od > 1 ? od : 1));
        g_norm_dst[idx] = rsqrtf((float)(id > 1 ? id : 1));
        g_norm_src[idx] = ns;
        g_h0n[idx] = (float)id * ns;
        atomicAdd(&g_cnt[n2g[idx]], 1.f);
    }
    s[t] = id;
    __syncthreads();
    #pragma unroll
    for (int off = CHUNK / 2; off > 0; off >>= 1) {
        if (t < off) s[t] += s[t + off];
        __syncthreads();
    }
    if (t == 0) g_part[blockIdx.x] = s[0];
}

// ---------------- scan partials (single tiny block) ----------------
__global__ void k_scanpart() {
    __shared__ int s[CHUNK];
    int t = threadIdx.x;
    s[t] = (t < NBLK) ? g_part[t] : 0;
    __syncthreads();
    #pragma unroll
    for (int off = 1; off < CHUNK; off <<= 1) {
        int v = (t >= off) ? s[t - off] : 0;
        __syncthreads();
        s[t] += v;
        __syncthreads();
    }
    if (t < NBLK) g_partoff[t] = (t == 0) ? 0 : s[t - 1];   // exclusive
    if (t == 0) g_row_off[N_NODES] = N_EDGES;               // total is known
}

// ---------------- per-block exclusive scan + block prefix ----------------
__global__ void k_offsets() {
    __shared__ int s[CHUNK];
    int t = threadIdx.x;
    int idx = blockIdx.x * CHUNK + t;
    int my = (idx < N_NODES) ? g_in_deg[idx] : 0;
    s[t] = my;
    __syncthreads();
    #pragma unroll
    for (int off = 1; off < CHUNK; off <<= 1) {
        int v = (t >= off) ? s[t - off] : 0;
        __syncthreads();
        s[t] += v;
        __syncthreads();
    }
    if (idx < N_NODES) {
        int ex = s[t] - my + g_partoff[blockIdx.x];   // exclusive prefix
        g_row_off[idx] = ex;
        g_cursor[idx]  = ex;
    }
}

// ---------------- bucket edges by dst ----------------
__global__ void k_bucket(const int* __restrict__ src, const int* __restrict__ dst) {
    int i = blockIdx.x * blockDim.x + threadIdx.x;
    if (i < N_EDGES) {
        int d = dst[i];
        int p = atomicAdd(&g_cursor[d], 1);
        g_edge_src[p] = src[i];
    }
}

// ---------------- layer 0: scalar aggregate -> outer product with W0 ----------------
// output pre-scaled by norm_src[v] for consumption by layer 1
__global__ void k_layer0(const float* __restrict__ W0, const float* __restrict__ b0) {
    int gtid = blockIdx.x * blockDim.x + threadIdx.x;
    int v = gtid >> 5;
    int lane = gtid & 31;
    if (v >= N_NODES) return;

    int beg = g_row_off[v], end = g_row_off[v + 1];
    float acc = 0.f;
    for (int e = beg + lane; e < end; e += 32) {
        acc += g_h0n[g_edge_src[e]];
    }
    #pragma unroll
    for (int off = 16; off; off >>= 1) acc += __shfl_xor_sync(0xffffffffu, acc, off);

    float x = acc * g_norm_dst[v];
    float ns = g_norm_src[v];
    float2 w = *(const float2*)&W0[2 * lane];
    float2 bb = *(const float2*)&b0[2 * lane];
    float2 o;
    o.x = fmaxf(fmaf(x, w.x, bb.x), 0.f) * ns;
    o.y = fmaxf(fmaf(x, w.y, bb.y), 0.f) * ns;
    *(float2*)&g_hA[v * HID + 2 * lane] = o;
}

// ---------------- feature layer: unrolled gather + fused 64x64 matvec + relu ----------------
// warp per node; lane owns features (2*lane, 2*lane+1). hin is already norm_src-scaled.
// mode 0: hA -> hB, output pre-scaled by norm_src (feeds next layer)
// mode 1: hB -> graph pool (atomicAdd into g_hg, no node store)
__global__ void __launch_bounds__(256) k_layer(const float* __restrict__ W,
                                               const float* __restrict__ b,
                                               const int* __restrict__ n2g,
                                               int mode) {
    __shared__ float sW[HID * HID];
    __shared__ float sb[HID];
    __shared__ float xs[8][HID];

    const float* hin  = mode ? g_hB : g_hA;

    int tid = threadIdx.x;
    for (int i = tid; i < HID * HID; i += 256) sW[i] = W[i];
    if (tid < HID) sb[tid] = b[tid];
    __syncthreads();

    int wib = tid >> 5;
    int lane = tid & 31;
    int v = blockIdx.x * 8 + wib;

    if (v < N_NODES) {
        int beg = g_row_off[v], end = g_row_off[v + 1];
        float a0 = 0.f, a1 = 0.f;
        int e = beg;
        // unroll-by-4: batch the index loads, keep 4 row loads in flight
        for (; e + 4 <= end; e += 4) {
            int s0 = g_edge_src[e];
            int s1 = g_edge_src[e + 1];
            int s2 = g_edge_src[e + 2];
            int s3 = g_edge_src[e + 3];
            float2 h0 = *(const float2*)&hin[s0 * HID + 2 * lane];
            float2 h1 = *(const float2*)&hin[s1 * HID + 2 * lane];
            float2 h2 = *(const float2*)&hin[s2 * HID + 2 * lane];
            float2 h3 = *(const float2*)&hin[s3 * HID + 2 * lane];
            a0 += (h0.x + h1.x) + (h2.x + h3.x);
            a1 += (h0.y + h1.y) + (h2.y + h3.y);
        }
        for (; e < end; e++) {
            int s = g_edge_src[e];
            float2 hv = *(const float2*)&hin[s * HID + 2 * lane];
            a0 += hv.x;
            a1 += hv.y;
        }
        float nd = g_norm_dst[v];
        xs[wib][2 * lane]     = a0 * nd;
        xs[wib][2 * lane + 1] = a1 * nd;
    }
    __syncwarp();

    if (v < N_NODES) {
        float o0 = sb[2 * lane], o1 = sb[2 * lane + 1];
        #pragma unroll
        for (int i = 0; i < HID; i++) {
            float xi = xs[wib][i];
            float2 w = *(const float2*)&sW[i * HID + 2 * lane];
            o0 = fmaf(xi, w.x, o0);
            o1 = fmaf(xi, w.y, o1);
        }
        o0 = fmaxf(o0, 0.f);
        o1 = fmaxf(o1, 0.f);
        if (mode == 0) {
            float ns = g_norm_src[v];       // pre-scale for next layer's gather
            float2 o; o.x = o0 * ns; o.y = o1 * ns;
            *(float2*)&g_hB[v * HID + 2 * lane] = o;
        } else {
            int g = n2g[v];                 // fused mean-pool accumulation
            atomicAdd(&g_hg[g * HID + 2 * lane],     o0);
            atomicAdd(&g_hg[g * HID + 2 * lane + 1], o1);
        }
    }
}

// ---------------- readout ----------------
__global__ void k_out(const float* __restrict__ Wr, const float* __restrict__ br,
                      float* __restrict__ out) {
    int gtid = blockIdx.x * blockDim.x + threadIdx.x;
    int g = gtid >> 5;
    int lane = gtid & 31;
    if (g >= N_GRAPHS) return;
    float inv = 1.f / fmaxf(g_cnt[g], 1.f);
    float2 hv = *(const float2*)&g_hg[g * HID + 2 * lane];
    float2 wr = *(const float2*)&Wr[2 * lane];
    float acc = hv.x * inv * wr.x + hv.y * inv * wr.y;
    #pragma unroll
    for (int off = 16; off; off >>= 1) acc += __shfl_xor_sync(0xffffffffu, acc, off);
    if (lane == 0) out[g] = acc + br[0];
}

// ---------------- launch ----------------
extern "C" void kernel_launch(void* const* d_in, const int* in_sizes, int n_in,
                              void* d_out, int out_size) {
    const int*   src = (const int*)d_in[0];
    const int*   dst = (const int*)d_in[1];
    const int*   n2g = (const int*)d_in[2];
    const float* W0  = (const float*)d_in[3];
    const float* b0  = (const float*)d_in[4];
    const float* W1  = (const float*)d_in[5];
    const float* b1  = (const float*)d_in[6];
    const float* W2  = (const float*)d_in[7];
    const float* b2  = (const float*)d_in[8];
    const float* Wr  = (const float*)d_in[9];
    const float* br  = (const float*)d_in[10];
    float* out = (float*)d_out;

    const int TB = 256;
    k_zero    <<<(N_NODES + TB - 1) / TB, TB>>>();
    k_deg     <<<(N_EDGES + TB - 1) / TB, TB>>>(src, dst);
    k_prep    <<<NBLK, CHUNK>>>(n2g);
    k_scanpart<<<1, CHUNK>>>();
    k_offsets <<<NBLK, CHUNK>>>();
    k_bucket  <<<(N_EDGES + TB - 1) / TB, TB>>>(src, dst);

    k_layer0<<<(N_NODES * 32 + TB - 1) / TB, TB>>>(W0, b0);
    k_layer <<<(N_NODES + 7) / 8, TB>>>(W1, b1, n2g, 0);  // hA -> hB (pre-scaled)
    k_layer <<<(N_NODES + 7) / 8, TB>>>(W2, b2, n2g, 1);  // hB -> pooled g_hg

    k_out   <<<(N_GRAPHS * 32 + TB - 1) / TB, TB>>>(Wr, br, out);
}

// round 14
// speedup vs baseline: 1.1173x; 1.1173x over previous
#include <cuda_runtime.h>

#define N_NODES  50000
#define N_EDGES  800000
#define N_GRAPHS 64
#define HID      64

#define CHUNK 256
#define NBLK ((N_NODES + CHUNK - 1) / CHUNK)   // 196

// ---------------- scratch (device globals; no allocation) ----------------
__device__ int    g_in_deg[N_NODES];
__device__ int    g_out_deg[N_NODES];
__device__ float  g_norm_src[N_NODES];
__device__ float  g_norm_dst[N_NODES];
__device__ float  g_h0n[N_NODES];         // in_deg * norm_src
__device__ float2 g_xn[N_NODES];          // (x0_v * ns_v, ns_v)  -- rank-1 layer-0 state
__device__ int    g_row_off[N_NODES + 1];
__device__ int    g_cursor[N_NODES];
__device__ int    g_edge_src[N_EDGES];
__device__ float  g_hA[N_NODES * HID];    // layer-2 output (unscaled)
__device__ float  g_hB[N_NODES * HID];    // layer-1 output, pre-scaled by norm_src
__device__ float  g_hg[N_GRAPHS * HID];
__device__ float  g_cnt[N_GRAPHS];
__device__ int    g_part[NBLK];

// ---------------- init ----------------
__global__ void k_zero() {
    int i = blockIdx.x * blockDim.x + threadIdx.x;
    if (i < N_NODES) { g_in_deg[i] = 0; g_out_deg[i] = 0; }
    if (i < N_GRAPHS * HID) g_hg[i] = 0.f;
    if (i < N_GRAPHS) g_cnt[i] = 0.f;
}

__global__ void k_deg(const int* __restrict__ src, const int* __restrict__ dst) {
    int i = blockIdx.x * blockDim.x + threadIdx.x;
    if (i < N_EDGES) {
        atomicAdd(&g_in_deg[dst[i]], 1);
        atomicAdd(&g_out_deg[src[i]], 1);
    }
}

// ---------------- prep: norms + h0n + per-block partial sums ----------------
__global__ void k_prep() {
    __shared__ int s[CHUNK];
    int t = threadIdx.x;
    int idx = blockIdx.x * CHUNK + t;
    int id = 0;
    if (idx < N_NODES) {
        id = g_in_deg[idx];
        int od = g_out_deg[idx];
        float ns = rsqrtf((float)(od > 1 ? od : 1));
        g_norm_dst[idx] = rsqrtf((float)(id > 1 ? id : 1));
        g_norm_src[idx] = ns;
        g_h0n[idx] = (float)id * ns;
    }
    s[t] = id;
    __syncthreads();
    #pragma unroll
    for (int off = CHUNK / 2; off > 0; off >>= 1) {
        if (t < off) s[t] += s[t + off];
        __syncthreads();
    }
    if (t == 0) g_part[blockIdx.x] = s[0];
    if (idx == 0) g_row_off[N_NODES] = N_EDGES;
}

// ---------------- offsets: block prefix (reduce partials below) + local scan ----------------
__global__ void k_offsets() {
    __shared__ int sp[CHUNK];
    __shared__ int s[CHUNK];
    int t = threadIdx.x;
    int bid = blockIdx.x;

    // prefix of this block = sum of partials with index < bid  (NBLK <= 256)
    sp[t] = (t < bid) ? g_part[t] : 0;
    __syncthreads();
    #pragma unroll
    for (int off = CHUNK / 2; off > 0; off >>= 1) {
        if (t < off) sp[t] += sp[t + off];
        __syncthreads();
    }
    int blockpre = sp[0];

    int idx = bid * CHUNK + t;
    int my = (idx < N_NODES) ? g_in_deg[idx] : 0;
    s[t] = my;
    __syncthreads();
    #pragma unroll
    for (int off = 1; off < CHUNK; off <<= 1) {
        int v = (t >= off) ? s[t - off] : 0;
        __syncthreads();
        s[t] += v;
        __syncthreads();
    }
    if (idx < N_NODES) {
        int ex = s[t] - my + blockpre;   // exclusive prefix
        g_row_off[idx] = ex;
        g_cursor[idx]  = ex;
    }
}

// ---------------- bucket edges by dst ----------------
__global__ void k_bucket(const int* __restrict__ src, const int* __restrict__ dst) {
    int i = blockIdx.x * blockDim.x + threadIdx.x;
    if (i < N_EDGES) {
        int d = dst[i];
        int p = atomicAdd(&g_cursor[d], 1);
        g_edge_src[p] = src[i];
    }
}

// ---------------- layer 0 (rank-1): scalar aggregate -> (x*ns, ns) pair ----------------
__global__ void k_x0() {
    int gtid = blockIdx.x * blockDim.x + threadIdx.x;
    int v = gtid >> 5;
    int lane = gtid & 31;
    if (v >= N_NODES) return;

    int beg = g_row_off[v], end = g_row_off[v + 1];
    float acc = 0.f;
    for (int e = beg + lane; e < end; e += 32) {
        acc += g_h0n[g_edge_src[e]];
    }
    #pragma unroll
    for (int off = 16; off; off >>= 1) acc += __shfl_xor_sync(0xffffffffu, acc, off);

    if (lane == 0) {
        float x  = acc * g_norm_dst[v];
        float ns = g_norm_src[v];
        float2 p; p.x = x * ns; p.y = ns;
        g_xn[v] = p;
    }
}

// ---------------- layer 1: rank-1 on-the-fly gather + fused 64x64 matvec ----------------
// per-edge message_f = max((x_s*ns_s)*W0_f + b0_f*ns_s, 0); only an 8B broadcast load per edge.
// output row pre-scaled by norm_src[v] for layer 2's gather.
__global__ void __launch_bounds__(256) k_layer1(const float* __restrict__ W0,
                                                const float* __restrict__ b0,
                                                const float* __restrict__ W1,
                                                const float* __restrict__ b1) {
    __shared__ float sW[HID * HID];
    __shared__ float sb[HID];
    __shared__ float xs[8][HID];

    int tid = threadIdx.x;
    for (int i = tid; i < HID * HID; i += 256) sW[i] = W1[i];
    if (tid < HID) sb[tid] = b1[tid];
    __syncthreads();

    int wib = tid >> 5;
    int lane = tid & 31;
    int v = blockIdx.x * 8 + wib;

    float w0a = W0[2 * lane], w0b = W0[2 * lane + 1];
    float b0a = b0[2 * lane], b0b = b0[2 * lane + 1];

    if (v < N_NODES) {
        int beg = g_row_off[v], end = g_row_off[v + 1];
        float a0 = 0.f, a1 = 0.f;
        int e = beg;
        for (; e + 4 <= end; e += 4) {
            int s0 = g_edge_src[e];
            int s1 = g_edge_src[e + 1];
            int s2 = g_edge_src[e + 2];
            int s3 = g_edge_src[e + 3];
            float2 p0 = g_xn[s0];
            float2 p1 = g_xn[s1];
            float2 p2 = g_xn[s2];
            float2 p3 = g_xn[s3];
            a0 += fmaxf(fmaf(p0.x, w0a, b0a * p0.y), 0.f)
                + fmaxf(fmaf(p1.x, w0a, b0a * p1.y), 0.f)
                + fmaxf(fmaf(p2.x, w0a, b0a * p2.y), 0.f)
                + fmaxf(fmaf(p3.x, w0a, b0a * p3.y), 0.f);
            a1 += fmaxf(fmaf(p0.x, w0b, b0b * p0.y), 0.f)
                + fmaxf(fmaf(p1.x, w0b, b0b * p1.y), 0.f)
                + fmaxf(fmaf(p2.x, w0b, b0b * p2.y), 0.f)
                + fmaxf(fmaf(p3.x, w0b, b0b * p3.y), 0.f);
        }
        for (; e < end; e++) {
            float2 p = g_xn[g_edge_src[e]];
            a0 += fmaxf(fmaf(p.x, w0a, b0a * p.y), 0.f);
            a1 += fmaxf(fmaf(p.x, w0b, b0b * p.y), 0.f);
        }
        float nd = g_norm_dst[v];
        xs[wib][2 * lane]     = a0 * nd;
        xs[wib][2 * lane + 1] = a1 * nd;
    }
    __syncwarp();

    if (v < N_NODES) {
        float o0 = sb[2 * lane], o1 = sb[2 * lane + 1];
        #pragma unroll
        for (int i = 0; i < HID; i++) {
            float xi = xs[wib][i];
            float2 w = *(const float2*)&sW[i * HID + 2 * lane];
            o0 = fmaf(xi, w.x, o0);
            o1 = fmaf(xi, w.y, o1);
        }
        float ns = g_norm_src[v];           // pre-scale for layer 2
        float2 o;
        o.x = fmaxf(o0, 0.f) * ns;
        o.y = fmaxf(o1, 0.f) * ns;
        *(float2*)&g_hB[v * HID + 2 * lane] = o;
    }
}

// ---------------- layer 2: row gather (input pre-scaled) + fused matvec ----------------
__global__ void __launch_bounds__(256) k_layer2(const float* __restrict__ W2,
                                                const float* __restrict__ b2) {
    __shared__ float sW[HID * HID];
    __shared__ float sb[HID];
    __shared__ float xs[8][HID];

    int tid = threadIdx.x;
    for (int i = tid; i < HID * HID; i += 256) sW[i] = W2[i];
    if (tid < HID) sb[tid] = b2[tid];
    __syncthreads();

    int wib = tid >> 5;
    int lane = tid & 31;
    int v = blockIdx.x * 8 + wib;

    if (v < N_NODES) {
        int beg = g_row_off[v], end = g_row_off[v + 1];
        float a0 = 0.f, a1 = 0.f;
        for (int e = beg; e < end; e++) {
            int s = g_edge_src[e];
            float2 hv = *(const float2*)&g_hB[s * HID + 2 * lane];
            a0 += hv.x;
            a1 += hv.y;
        }
        float nd = g_norm_dst[v];
        xs[wib][2 * lane]     = a0 * nd;
        xs[wib][2 * lane + 1] = a1 * nd;
    }
    __syncwarp();

    if (v < N_NODES) {
        float o0 = sb[2 * lane], o1 = sb[2 * lane + 1];
        #pragma unroll
        for (int i = 0; i < HID; i++) {
            float xi = xs[wib][i];
            float2 w = *(const float2*)&sW[i * HID + 2 * lane];
            o0 = fmaf(xi, w.x, o0);
            o1 = fmaf(xi, w.y, o1);
        }
        float2 o;
        o.x = fmaxf(o0, 0.f);
        o.y = fmaxf(o1, 0.f);
        *(float2*)&g_hA[v * HID + 2 * lane] = o;
    }
}

// ---------------- graph pooling (mean) ----------------
__global__ void k_pool(const int* __restrict__ n2g) {
    int gtid = blockIdx.x * blockDim.x + threadIdx.x;
    int v = gtid >> 5;
    int lane = gtid & 31;
    if (v >= N_NODES) return;
    int g = n2g[v];
    float2 hv = *(const float2*)&g_hA[v * HID + 2 * lane];
    atomicAdd(&g_hg[g * HID + 2 * lane], hv.x);
    atomicAdd(&g_hg[g * HID + 2 * lane + 1], hv.y);
    if (lane == 0) atomicAdd(&g_cnt[g], 1.f);
}

// ---------------- readout ----------------
__global__ void k_out(const float* __restrict__ Wr, const float* __restrict__ br,
                      float* __restrict__ out) {
    int gtid = blockIdx.x * blockDim.x + threadIdx.x;
    int g = gtid >> 5;
    int lane = gtid & 31;
    if (g >= N_GRAPHS) return;
    float inv = 1.f / fmaxf(g_cnt[g], 1.f);
    float2 hv = *(const float2*)&g_hg[g * HID + 2 * lane];
    float2 wr = *(const float2*)&Wr[2 * lane];
    float acc = hv.x * inv * wr.x + hv.y * inv * wr.y;
    #pragma unroll
    for (int off = 16; off; off >>= 1) acc += __shfl_xor_sync(0xffffffffu, acc, off);
    if (lane == 0) out[g] = acc + br[0];
}

// ---------------- launch ----------------
extern "C" void kernel_launch(void* const* d_in, const int* in_sizes, int n_in,
                              void* d_out, int out_size) {
    const int*   src = (const int*)d_in[0];
    const int*   dst = (const int*)d_in[1];
    const int*   n2g = (const int*)d_in[2];
    const float* W0  = (const float*)d_in[3];
    const float* b0  = (const float*)d_in[4];
    const float* W1  = (const float*)d_in[5];
    const float* b1  = (const float*)d_in[6];
    const float* W2  = (const float*)d_in[7];
    const float* b2  = (const float*)d_in[8];
    const float* Wr  = (const float*)d_in[9];
    const float* br  = (const float*)d_in[10];
    float* out = (float*)d_out;

    const int TB = 256;
    k_zero   <<<(N_NODES + TB - 1) / TB, TB>>>();
    k_deg    <<<(N_EDGES + TB - 1) / TB, TB>>>(src, dst);
    k_prep   <<<NBLK, CHUNK>>>();
    k_offsets<<<NBLK, CHUNK>>>();
    k_bucket <<<(N_EDGES + TB - 1) / TB, TB>>>(src, dst);

    k_x0     <<<(N_NODES * 32 + TB - 1) / TB, TB>>>();
    k_layer1 <<<(N_NODES + 7) / 8, TB>>>(W0, b0, W1, b1);
    k_layer2 <<<(N_NODES + 7) / 8, TB>>>(W2, b2);

    k_pool   <<<(N_NODES * 32 + TB - 1) / TB, TB>>>(n2g);
    k_out    <<<(N_GRAPHS * 32 + TB - 1) / TB, TB>>>(Wr, br, out);
}

// round 15
// speedup vs baseline: 1.3910x; 1.2449x over previous
#include <cuda_runtime.h>

#define N_NODES  50000
#define N_EDGES  800000
#define N_GRAPHS 64
#define HID      64

#define CHUNK 256
#define NBLK ((N_NODES + CHUNK - 1) / CHUNK)   // 196

// ---------------- scratch (device globals; no allocation) ----------------
__device__ int    g_in_deg[N_NODES];
__device__ int    g_out_deg[N_NODES];
__device__ float  g_norm_src[N_NODES];
__device__ float  g_norm_dst[N_NODES];
__device__ float  g_h0n[N_NODES];         // in_deg * norm_src
__device__ float2 g_xn[N_NODES];          // (x0_v * ns_v, ns_v)  -- rank-1 layer-0 state
__device__ int    g_row_off[N_NODES + 1];
__device__ int    g_cursor[N_NODES];
__device__ int    g_edge_src[N_EDGES];
__device__ float  g_hA[N_NODES * HID];    // layer-2 output (unscaled)
__device__ float  g_hB[N_NODES * HID];    // layer-1 output, pre-scaled by norm_src
__device__ float  g_hg[N_GRAPHS * HID];
__device__ float  g_cnt[N_GRAPHS];
__device__ int    g_part[NBLK];

// ---------------- init ----------------
__global__ void k_zero() {
    int i = blockIdx.x * blockDim.x + threadIdx.x;
    if (i < N_NODES) { g_in_deg[i] = 0; g_out_deg[i] = 0; }
    if (i < N_GRAPHS * HID) g_hg[i] = 0.f;
    if (i < N_GRAPHS) g_cnt[i] = 0.f;
}

__global__ void k_deg(const int* __restrict__ src, const int* __restrict__ dst) {
    int i = blockIdx.x * blockDim.x + threadIdx.x;
    if (i < N_EDGES) {
        atomicAdd(&g_in_deg[dst[i]], 1);
        atomicAdd(&g_out_deg[src[i]], 1);
    }
}

// ---------------- prep: norms + h0n + per-block partial sums ----------------
__global__ void k_prep() {
    __shared__ int s[CHUNK];
    int t = threadIdx.x;
    int idx = blockIdx.x * CHUNK + t;
    int id = 0;
    if (idx < N_NODES) {
        id = g_in_deg[idx];
        int od = g_out_deg[idx];
        float ns = rsqrtf((float)(od > 1 ? od : 1));
        g_norm_dst[idx] = rsqrtf((float)(id > 1 ? id : 1));
        g_norm_src[idx] = ns;
        g_h0n[idx] = (float)id * ns;
    }
    s[t] = id;
    __syncthreads();
    #pragma unroll
    for (int off = CHUNK / 2; off > 0; off >>= 1) {
        if (t < off) s[t] += s[t + off];
        __syncthreads();
    }
    if (t == 0) g_part[blockIdx.x] = s[0];
    if (idx == 0) g_row_off[N_NODES] = N_EDGES;
}

// ---------------- offsets: block prefix (reduce partials below) + local scan ----------------
__global__ void k_offsets() {
    __shared__ int sp[CHUNK];
    __shared__ int s[CHUNK];
    int t = threadIdx.x;
    int bid = blockIdx.x;

    sp[t] = (t < bid) ? g_part[t] : 0;
    __syncthreads();
    #pragma unroll
    for (int off = CHUNK / 2; off > 0; off >>= 1) {
        if (t < off) sp[t] += sp[t + off];
        __syncthreads();
    }
    int blockpre = sp[0];

    int idx = bid * CHUNK + t;
    int my = (idx < N_NODES) ? g_in_deg[idx] : 0;
    s[t] = my;
    __syncthreads();
    #pragma unroll
    for (int off = 1; off < CHUNK; off <<= 1) {
        int v = (t >= off) ? s[t - off] : 0;
        __syncthreads();
        s[t] += v;
        __syncthreads();
    }
    if (idx < N_NODES) {
        int ex = s[t] - my + blockpre;   // exclusive prefix
        g_row_off[idx] = ex;
        g_cursor[idx]  = ex;
    }
}

// ---------------- bucket edges by dst ----------------
__global__ void k_bucket(const int* __restrict__ src, const int* __restrict__ dst) {
    int i = blockIdx.x * blockDim.x + threadIdx.x;
    if (i < N_EDGES) {
        int d = dst[i];
        int p = atomicAdd(&g_cursor[d], 1);
        g_edge_src[p] = src[i];
    }
}

// ---------------- layer 0 (rank-1): scalar aggregate -> (x*ns, ns) pair ----------------
__global__ void k_x0() {
    int gtid = blockIdx.x * blockDim.x + threadIdx.x;
    int v = gtid >> 5;
    int lane = gtid & 31;
    if (v >= N_NODES) return;

    int beg = g_row_off[v], end = g_row_off[v + 1];
    float acc = 0.f;
    for (int e = beg + lane; e < end; e += 32) {
        acc += g_h0n[g_edge_src[e]];
    }
    #pragma unroll
    for (int off = 16; off; off >>= 1) acc += __shfl_xor_sync(0xffffffffu, acc, off);

    if (lane == 0) {
        float x  = acc * g_norm_dst[v];
        float ns = g_norm_src[v];
        float2 p; p.x = x * ns; p.y = ns;
        g_xn[v] = p;
    }
}

// ---------------- layer 1: rank-1 on-the-fly gather + fused 64x64 matvec ----------------
__global__ void __launch_bounds__(256) k_layer1(const float* __restrict__ W0,
                                                const float* __restrict__ b0,
                                                const float* __restrict__ W1,
                                                const float* __restrict__ b1) {
    __shared__ float sW[HID * HID];
    __shared__ float sb[HID];
    __shared__ float xs[8][HID];

    int tid = threadIdx.x;
    for (int i = tid; i < HID * HID; i += 256) sW[i] = W1[i];
    if (tid < HID) sb[tid] = b1[tid];
    __syncthreads();

    int wib = tid >> 5;
    int lane = tid & 31;
    int v = blockIdx.x * 8 + wib;

    float w0a = W0[2 * lane], w0b = W0[2 * lane + 1];
    float b0a = b0[2 * lane], b0b = b0[2 * lane + 1];

    if (v < N_NODES) {
        int beg = g_row_off[v], end = g_row_off[v + 1];
        float a0 = 0.f, a1 = 0.f;
        int e = beg;
        for (; e + 4 <= end; e += 4) {
            int s0 = g_edge_src[e];
            int s1 = g_edge_src[e + 1];
            int s2 = g_edge_src[e + 2];
            int s3 = g_edge_src[e + 3];
            float2 p0 = g_xn[s0];
            float2 p1 = g_xn[s1];
            float2 p2 = g_xn[s2];
            float2 p3 = g_xn[s3];
            a0 += fmaxf(fmaf(p0.x, w0a, b0a * p0.y), 0.f)
                + fmaxf(fmaf(p1.x, w0a, b0a * p1.y), 0.f)
                + fmaxf(fmaf(p2.x, w0a, b0a * p2.y), 0.f)
                + fmaxf(fmaf(p3.x, w0a, b0a * p3.y), 0.f);
            a1 += fmaxf(fmaf(p0.x, w0b, b0b * p0.y), 0.f)
                + fmaxf(fmaf(p1.x, w0b, b0b * p1.y), 0.f)
                + fmaxf(fmaf(p2.x, w0b, b0b * p2.y), 0.f)
                + fmaxf(fmaf(p3.x, w0b, b0b * p3.y), 0.f);
        }
        for (; e < end; e++) {
            float2 p = g_xn[g_edge_src[e]];
            a0 += fmaxf(fmaf(p.x, w0a, b0a * p.y), 0.f);
            a1 += fmaxf(fmaf(p.x, w0b, b0b * p.y), 0.f);
        }
        float nd = g_norm_dst[v];
        xs[wib][2 * lane]     = a0 * nd;
        xs[wib][2 * lane + 1] = a1 * nd;
    }
    __syncwarp();

    if (v < N_NODES) {
        float o0 = sb[2 * lane], o1 = sb[2 * lane + 1];
        #pragma unroll
        for (int i = 0; i < HID; i++) {
            float xi = xs[wib][i];
            float2 w = *(const float2*)&sW[i * HID + 2 * lane];
            o0 = fmaf(xi, w.x, o0);
            o1 = fmaf(xi, w.y, o1);
        }
        float ns = g_norm_src[v];           // pre-scale for layer 2
        float2 o;
        o.x = fmaxf(o0, 0.f) * ns;
        o.y = fmaxf(o1, 0.f) * ns;
        *(float2*)&g_hB[v * HID + 2 * lane] = o;
    }
}

// ---------------- layer 2: half-warp-per-node float4 gather + fused matvec ----------------
// 16 lanes per node; lane owns features 4*sub .. 4*sub+3. 2 nodes per warp
// (independent edge chains -> doubled MLP), unroll-4 batched index loads.
__global__ void __launch_bounds__(256) k_layer2(const float* __restrict__ W2,
                                                const float* __restrict__ b2) {
    __shared__ float sW[HID * HID];
    __shared__ float sb[HID];
    __shared__ float xs[16][HID];

    int tid = threadIdx.x;
    for (int i = tid; i < HID * HID; i += 256) sW[i] = W2[i];
    if (tid < HID) sb[tid] = b2[tid];
    __syncthreads();

    int hw  = tid >> 4;        // half-warp id in block: 0..15
    int sub = tid & 15;        // lane in half-warp
    int v = blockIdx.x * 16 + hw;

    if (v < N_NODES) {
        int beg = g_row_off[v], end = g_row_off[v + 1];
        float4 a = make_float4(0.f, 0.f, 0.f, 0.f);
        int e = beg;
        for (; e + 4 <= end; e += 4) {
            int s0 = g_edge_src[e];
            int s1 = g_edge_src[e + 1];
            int s2 = g_edge_src[e + 2];
            int s3 = g_edge_src[e + 3];
            float4 h0 = *(const float4*)&g_hB[s0 * HID + 4 * sub];
            float4 h1 = *(const float4*)&g_hB[s1 * HID + 4 * sub];
            float4 h2 = *(const float4*)&g_hB[s2 * HID + 4 * sub];
            float4 h3 = *(const float4*)&g_hB[s3 * HID + 4 * sub];
            a.x += (h0.x + h1.x) + (h2.x + h3.x);
            a.y += (h0.y + h1.y) + (h2.y + h3.y);
            a.z += (h0.z + h1.z) + (h2.z + h3.z);
            a.w += (h0.w + h1.w) + (h2.w + h3.w);
        }
        for (; e < end; e++) {
            int s = g_edge_src[e];
            float4 hv = *(const float4*)&g_hB[s * HID + 4 * sub];
            a.x += hv.x; a.y += hv.y; a.z += hv.z; a.w += hv.w;
        }
        float nd = g_norm_dst[v];
        a.x *= nd; a.y *= nd; a.z *= nd; a.w *= nd;
        *(float4*)&xs[hw][4 * sub] = a;
    }
    __syncwarp();

    if (v < N_NODES) {
        float4 o = *(const float4*)&sb[4 * sub];
        #pragma unroll
        for (int i = 0; i < HID; i++) {
            float xi = xs[hw][i];
            float4 w = *(const float4*)&sW[i * HID + 4 * sub];
            o.x = fmaf(xi, w.x, o.x);
            o.y = fmaf(xi, w.y, o.y);
            o.z = fmaf(xi, w.z, o.z);
            o.w = fmaf(xi, w.w, o.w);
        }
        o.x = fmaxf(o.x, 0.f);
        o.y = fmaxf(o.y, 0.f);
        o.z = fmaxf(o.z, 0.f);
        o.w = fmaxf(o.w, 0.f);
        *(float4*)&g_hA[v * HID + 4 * sub] = o;
    }
}

// ---------------- graph pooling: exploit sorted node2graph (run-length flush) ----------------
// warp scans NODES_PER_WARP contiguous nodes; accumulates while graph id unchanged,
// flushes one atomic per run. ~850 flushes total instead of 1.6M atomics.
#define NODES_PER_WARP 64
#define POOL_WARPS ((N_NODES + NODES_PER_WARP - 1) / NODES_PER_WARP)   // 782

__global__ void k_pool(const int* __restrict__ n2g) {
    int gtid = blockIdx.x * blockDim.x + threadIdx.x;
    int w = gtid >> 5;
    int lane = gtid & 31;
    if (w >= POOL_WARPS) return;

    int v0 = w * NODES_PER_WARP;
    int v1 = v0 + NODES_PER_WARP; if (v1 > N_NODES) v1 = N_NODES;

    int   cur = n2g[v0];
    float a0 = 0.f, a1 = 0.f;
    float cnt = 0.f;

    for (int v = v0; v < v1; v++) {
        int g = n2g[v];
        if (g != cur) {
            atomicAdd(&g_hg[cur * HID + 2 * lane],     a0);
            atomicAdd(&g_hg[cur * HID + 2 * lane + 1], a1);
            if (lane == 0) atomicAdd(&g_cnt[cur], cnt);
            cur = g; a0 = 0.f; a1 = 0.f; cnt = 0.f;
        }
        float2 hv = *(const float2*)&g_hA[v * HID + 2 * lane];
        a0 += hv.x;
        a1 += hv.y;
        cnt += 1.f;
    }
    atomicAdd(&g_hg[cur * HID + 2 * lane],     a0);
    atomicAdd(&g_hg[cur * HID + 2 * lane + 1], a1);
    if (lane == 0) atomicAdd(&g_cnt[cur], cnt);
}

// ---------------- readout ----------------
__global__ void k_out(const float* __restrict__ Wr, const float* __restrict__ br,
                      float* __restrict__ out) {
    int gtid = blockIdx.x * blockDim.x + threadIdx.x;
    int g = gtid >> 5;
    int lane = gtid & 31;
    if (g >= N_GRAPHS) return;
    float inv = 1.f / fmaxf(g_cnt[g], 1.f);
    float2 hv = *(const float2*)&g_hg[g * HID + 2 * lane];
    float2 wr = *(const float2*)&Wr[2 * lane];
    float acc = hv.x * inv * wr.x + hv.y * inv * wr.y;
    #pragma unroll
    for (int off = 16; off; off >>= 1) acc += __shfl_xor_sync(0xffffffffu, acc, off);
    if (lane == 0) out[g] = acc + br[0];
}

// ---------------- launch ----------------
extern "C" void kernel_launch(void* const* d_in, const int* in_sizes, int n_in,
                              void* d_out, int out_size) {
    const int*   src = (const int*)d_in[0];
    const int*   dst = (const int*)d_in[1];
    const int*   n2g = (const int*)d_in[2];
    const float* W0  = (const float*)d_in[3];
    const float* b0  = (const float*)d_in[4];
    const float* W1  = (const float*)d_in[5];
    const float* b1  = (const float*)d_in[6];
    const float* W2  = (const float*)d_in[7];
    const float* b2  = (const float*)d_in[8];
    const float* Wr  = (const float*)d_in[9];
    const float* br  = (const float*)d_in[10];
    float* out = (float*)d_out;

    const int TB = 256;
    k_zero   <<<(N_NODES + TB - 1) / TB, TB>>>();
    k_deg    <<<(N_EDGES + TB - 1) / TB, TB>>>(src, dst);
    k_prep   <<<NBLK, CHUNK>>>();
    k_offsets<<<NBLK, CHUNK>>>();
    k_bucket <<<(N_EDGES + TB - 1) / TB, TB>>>(src, dst);

    k_x0     <<<(N_NODES * 32 + TB - 1) / TB, TB>>>();
    k_layer1 <<<(N_NODES + 7) / 8, TB>>>(W0, b0, W1, b1);
    k_layer2 <<<(N_NODES + 15) / 16, TB>>>(W2, b2);

    k_pool   <<<(POOL_WARPS * 32 + TB - 1) / TB, TB>>>(n2g);
    k_out    <<<(N_GRAPHS * 32 + TB - 1) / TB, TB>>>(Wr, br, out);
}